// round 12
// baseline (speedup 1.0000x reference)
#include <cuda_runtime.h>
#include <cuda_bf16.h>
#include <math.h>
#include <stdint.h>

#define PB 8
#define PN 256

// ---------------- scratch ----------------
__device__ float g_node[PB * PN * 64];
__device__ float g_T[PB * PN * 64];
__device__ __align__(16) uint32_t g_node_h[PB * PN * 32];
__device__ __align__(16) uint32_t g_node_l[PB * PN * 32];
// fragment-ordered weights, vec4 interleaved: word = ((t*S+s)*32+lane)*4 + {h0,h1,l0,l1}
__device__ __align__(16) uint32_t g_wimg[14336];

#define W1_O 0          // S=6: 48*32*4 = 6144 words
#define W2_O 6144       // S=4: 32*32*4 = 4096
#define W3_O 10240      // S=4: 4096
#define WIMG_WORDS 14336

#define A_STR 52
#define AH_O  WIMG_WORDS
#define AL_O  (WIMG_WORDS + 256 * A_STR)
#define SMEM_WORDS (WIMG_WORDS + 2 * 256 * A_STR)   // 40960 words = 163840 B

// res.lo = x0, res.hi = x1
#define PACK_BF16X2(res, x0, x1) \
    asm("cvt.rn.satfinite.bf16x2.f32 %0, %1, %2;" : "=r"(res) : "f"(x1), "f"(x0))

#define MMA_BF16(c, a, b0, b1) \
    asm volatile("mma.sync.aligned.m16n8k16.row.col.f32.bf16.bf16.f32 " \
        "{%0,%1,%2,%3}, {%4,%5,%6,%7}, {%8,%9}, {%0,%1,%2,%3};" \
        : "+f"((c)[0]), "+f"((c)[1]), "+f"((c)[2]), "+f"((c)[3]) \
        : "r"((a)[0]), "r"((a)[1]), "r"((a)[2]), "r"((a)[3]), "r"(b0), "r"(b1))

// exp(-x) for x >= 0, poly exp2 (no MUFU), rel err ~1.5e-4
__device__ __forceinline__ float fexp_neg(float x) {
    float y = -x * 1.44269504f;
    if (y < -126.0f) return 0.0f;
    float n = floorf(y);
    float f = y - n;
    float p = 1.0f + f * (0.6931472f + f * (0.2402265f + f * (0.0555041f +
              f * (0.0096181f + f * 0.0013333f))));
    return p * __int_as_float(((int)n + 127) << 23);
}

__device__ __forceinline__ void split_pack(float x0, float x1, uint32_t& h, uint32_t& l) {
    PACK_BF16X2(h, x0, x1);
    float e0 = x0 - __bfloat162float(__float2bfloat16_rn(x0));
    float e1 = x1 - __bfloat162float(__float2bfloat16_rn(x1));
    PACK_BF16X2(l, e0, e1);
}

// ================= Kernel 1: node embed + LN + T + bf16 hi/lo pack =================
__global__ __launch_bounds__(256) void k_node_prep(
    const int* __restrict__ atom, const float* __restrict__ emb,
    const float* __restrict__ ne_w, const float* __restrict__ ne_b,
    const float* __restrict__ ne_g, const float* __restrict__ ne_beta,
    const float* __restrict__ ee_w1)
{
    int y = threadIdx.y, c = threadIdx.x;
    int row = blockIdx.x * 4 + y;
    __shared__ float s_in[4][64], s_node[4][64], s_red[4][2];

    int a = atom[row];
    s_in[y][c] = fmaxf(emb[a * 64 + c], 0.0f);
    __syncthreads();

    float acc = ne_b[c];
#pragma unroll 8
    for (int k = 0; k < 64; k++) acc += s_in[y][k] * ne_w[k * 64 + c];

    float v = acc;
#pragma unroll
    for (int o = 16; o; o >>= 1) v += __shfl_xor_sync(0xffffffffu, v, o);
    if ((c & 31) == 0) s_red[y][c >> 5] = v;
    __syncthreads();
    float mean = (s_red[y][0] + s_red[y][1]) * (1.0f / 64.0f);
    float d = acc - mean;
    v = d * d;
#pragma unroll
    for (int o = 16; o; o >>= 1) v += __shfl_xor_sync(0xffffffffu, v, o);
    __syncthreads();
    if ((c & 31) == 0) s_red[y][c >> 5] = v;
    __syncthreads();
    float var = (s_red[y][0] + s_red[y][1]) * (1.0f / 64.0f);
    float nv = d * rsqrtf(var + 1e-5f) * ne_g[c] + ne_beta[c];

    g_node[row * 64 + c] = nv;
    s_node[y][c] = nv;
    __syncthreads();

    float tacc = 0.0f;
#pragma unroll 8
    for (int k = 0; k < 64; k++) tacc += s_node[y][k] * ee_w1[(64 + k) * 64 + c];
    g_T[row * 64 + c] = tacc;

    if (c < 32) {
        uint32_t hi, lo;
        split_pack(s_node[y][2 * c], s_node[y][2 * c + 1], hi, lo);
        g_node_h[row * 32 + c] = hi;
        g_node_l[row * 32 + c] = lo;
    }
}

// ================= Kernel 1b: fragment-ordered weight images (vec4) =================
// k = s*16 + (lane%4)*2 + reg*8 (w0=k, w1=k+1), n = t*8 + lane/4
__device__ __forceinline__ void wimg_put4(uint32_t* base, int ts, int lane, int reg,
                                          float w0, float w1) {
    uint32_t h, l;
    split_pack(w0, w1, h, l);
    base[(ts * 32 + lane) * 4 + reg]     = h;
    base[(ts * 32 + lane) * 4 + 2 + reg] = l;
}

__global__ __launch_bounds__(256) void k_wprep(
    const float* __restrict__ ee_w1, const float* __restrict__ ee_w2,
    const float* __restrict__ ee_w3)
{
    int tid = threadIdx.x;
    // Layer 1: S=6, K=96: k<32 -> Wr (ee_w1 rows 128..159), else Ws (rows 0..63)
    for (int idx = tid; idx < 3072; idx += 256) {
        int reg = idx & 1, lane = (idx >> 1) & 31, ts = idx >> 6;
        int s = ts % 6, t = ts / 6;
        int k = s * 16 + (lane & 3) * 2 + reg * 8;
        int n = t * 8 + (lane >> 2);
        float w0 = (k < 32)     ? ee_w1[(128 + k) * 64 + n] : ee_w1[(k - 32) * 64 + n];
        float w1 = (k + 1 < 32) ? ee_w1[(129 + k) * 64 + n] : ee_w1[(k - 31) * 64 + n];
        wimg_put4(&g_wimg[W1_O], ts, lane, reg, w0, w1);
    }
    // Layers 2/3: S=4, K=64
    for (int idx = tid; idx < 2048; idx += 256) {
        int reg = idx & 1, lane = (idx >> 1) & 31, ts = idx >> 6;
        int s = ts & 3, t = ts >> 2;
        int k = s * 16 + (lane & 3) * 2 + reg * 8;
        int n = t * 8 + (lane >> 2);
        wimg_put4(&g_wimg[W2_O], ts, lane, reg, ee_w2[k * 64 + n], ee_w2[(k + 1) * 64 + n]);
        wimg_put4(&g_wimg[W3_O], ts, lane, reg, ee_w3[k * 64 + n], ee_w3[(k + 1) * 64 + n]);
    }
}

// ---- one MLP layer, 2 rowsets (32 rows) per warp, s-outer / t-inner ----
template <int S>
__device__ __forceinline__ void do_layer(
    const uint32_t* __restrict__ sAh, const uint32_t* __restrict__ sAl,
    const uint32_t* __restrict__ w, int rb0, int rb1, int lane,
    float c0[8][4], float c1[8][4])
{
    const int cw = lane & 3;
#pragma unroll
    for (int s = 0; s < S; s++) {
        uint32_t a0h[4], a0l[4], a1h[4], a1l[4];
        {
            const uint32_t* p = sAh + rb0 * A_STR + s * 8 + cw;
            const uint32_t* q = sAh + (rb0 + 8) * A_STR + s * 8 + cw;
            a0h[0] = p[0]; a0h[1] = q[0]; a0h[2] = p[4]; a0h[3] = q[4];
            p = sAl + rb0 * A_STR + s * 8 + cw;
            q = sAl + (rb0 + 8) * A_STR + s * 8 + cw;
            a0l[0] = p[0]; a0l[1] = q[0]; a0l[2] = p[4]; a0l[3] = q[4];
            p = sAh + rb1 * A_STR + s * 8 + cw;
            q = sAh + (rb1 + 8) * A_STR + s * 8 + cw;
            a1h[0] = p[0]; a1h[1] = q[0]; a1h[2] = p[4]; a1h[3] = q[4];
            p = sAl + rb1 * A_STR + s * 8 + cw;
            q = sAl + (rb1 + 8) * A_STR + s * 8 + cw;
            a1l[0] = p[0]; a1l[1] = q[0]; a1l[2] = p[4]; a1l[3] = q[4];
        }
#pragma unroll
        for (int t = 0; t < 8; t++) {
            uint4 bv = *(const uint4*)&w[((t * S + s) * 32 + lane) * 4];
            MMA_BF16(c0[t], a0h, bv.x, bv.y);
            MMA_BF16(c0[t], a0l, bv.x, bv.y);
            MMA_BF16(c0[t], a0h, bv.z, bv.w);
            MMA_BF16(c1[t], a1h, bv.x, bv.y);
            MMA_BF16(c1[t], a1l, bv.x, bv.y);
            MMA_BF16(c1[t], a1h, bv.z, bv.w);
        }
    }
}

// ---- epilogue: bias + relu + hi/lo split back into A buffer (one rowset) ----
__device__ __forceinline__ void epi_write(
    float c[8][4], const float* __restrict__ bias,
    uint32_t* __restrict__ sAh, uint32_t* __restrict__ sAl, int rb, int lane)
{
    uint32_t* w0h = sAh + rb * A_STR;
    uint32_t* w1h = sAh + (rb + 8) * A_STR;
    uint32_t* w0l = sAl + rb * A_STR;
    uint32_t* w1l = sAl + (rb + 8) * A_STR;
    const int cw = lane & 3;
#pragma unroll
    for (int t = 0; t < 8; t++) {
        float2 bv = *(const float2*)&bias[t * 8 + cw * 2];
        float x0 = fmaxf(c[t][0] + bv.x, 0.0f);
        float x1 = fmaxf(c[t][1] + bv.y, 0.0f);
        float x2 = fmaxf(c[t][2] + bv.x, 0.0f);
        float x3 = fmaxf(c[t][3] + bv.y, 0.0f);
        uint32_t h, l;
        split_pack(x0, x1, h, l);
        w0h[t * 4 + cw] = h; w0l[t * 4 + cw] = l;
        split_pack(x2, x3, h, l);
        w1h[t * 4 + cw] = h; w1l[t * 4 + cw] = l;
    }
}

// ================= Kernel 2: mma.sync edge MLP =================
// Block per (b,i), 256 threads (8 warps x 32 rows), single 256-row chunk.
__global__ __launch_bounds__(256) void k_edge(
    const float* __restrict__ pos, const float* __restrict__ mask,
    const float* __restrict__ ee_b1, const float* __restrict__ ee_b2,
    const float* __restrict__ ee_b3, const float* __restrict__ ee_g,
    const float* __restrict__ ee_beta, float* __restrict__ edge_out)
{
    extern __shared__ uint32_t sw[];
    __shared__ float s_Tp[64], s_b2[64], s_b3[64], s_g[64], s_be[64];

    const int tid = threadIdx.x;
    const int wid = tid >> 5;
    const int lane = tid & 31;
    const int bi = blockIdx.x;
    const int b = bi >> 8;

    // stage weight images once
    {
        const uint4* src = (const uint4*)g_wimg;
        uint4* dst = (uint4*)sw;
        for (int i = tid; i < WIMG_WORDS / 4; i += 256) dst[i] = src[i];
    }
    if (tid < 64) {
        s_Tp[tid] = g_T[bi * 64 + tid] + ee_b1[tid];
        s_b2[tid] = ee_b2[tid];
        s_b3[tid] = ee_b3[tid];
        s_g[tid]  = ee_g[tid];
        s_be[tid] = ee_beta[tid];
    }

    uint32_t* sAh = sw + AH_O;
    uint32_t* sAl = sw + AL_O;

    const float px = pos[bi * 3 + 0];
    const float py = pos[bi * 3 + 1];
    const float pz = pos[bi * 3 + 2];

    // ---- build A1 = [rbf(32) | node(64)] for rows 0..255 (one row per thread) ----
    {
        const int row = tid;
        const int gj = b * 256 + row;
        float qx = pos[gj * 3 + 0], qy = pos[gj * 3 + 1], qz = pos[gj * 3 + 2];
        float mk = mask[bi * 256 + row];
        float dx = px - qx, dy = py - qy, dz = pz - qz;
        float dist = sqrtf(dx * dx + dy * dy + dz * dz + 1e-10f) * mk;
        uint32_t* rh = sAh + row * A_STR;
        uint32_t* rl = sAl + row * A_STR;
#pragma unroll
        for (int w = 0; w < 16; w++) {
            float t0 = (dist - (20.0f / 31.0f) * (float)(2 * w)) * 1.6f;
            float t1 = (dist - (20.0f / 31.0f) * (float)(2 * w + 1)) * 1.6f;
            float x0 = fexp_neg(t0 * t0) * mk;
            float x1 = fexp_neg(t1 * t1) * mk;
            uint32_t h, l;
            split_pack(x0, x1, h, l);
            rh[w] = h; rl[w] = l;
        }
        const uint4* nh = (const uint4*)(g_node_h + gj * 32);
        const uint4* nl = (const uint4*)(g_node_l + gj * 32);
#pragma unroll
        for (int q = 0; q < 8; q++) {
            *(uint4*)&rh[16 + 4 * q] = nh[q];
            *(uint4*)&rl[16 + 4 * q] = nl[q];
        }
    }
    __syncthreads();

    const int rb0 = wid * 32 + (lane >> 2);        // rowset 0: rows rb0, rb0+8
    const int rb1 = rb0 + 16;                      // rowset 1
    const int cw = lane & 3;

    // ---- layer 1 (K=96) ----
    {
        float c0[8][4] = {}, c1[8][4] = {};
        do_layer<6>(sAh, sAl, sw + W1_O, rb0, rb1, lane, c0, c1);
        epi_write(c0, s_Tp, sAh, sAl, rb0, lane);
        epi_write(c1, s_Tp, sAh, sAl, rb1, lane);
    }
    __syncwarp();
    // ---- layer 2 (K=64) ----
    {
        float c0[8][4] = {}, c1[8][4] = {};
        do_layer<4>(sAh, sAl, sw + W2_O, rb0, rb1, lane, c0, c1);
        epi_write(c0, s_b2, sAh, sAl, rb0, lane);
        epi_write(c1, s_b2, sAh, sAl, rb1, lane);
    }
    __syncwarp();
    // ---- layer 3 (K=64) + LayerNorm + store ----
    {
        float c0[8][4] = {}, c1[8][4] = {};
        do_layer<4>(sAh, sAl, sw + W3_O, rb0, rb1, lane, c0, c1);
#pragma unroll
        for (int rs = 0; rs < 2; rs++) {
            float (*c)[4] = rs ? c1 : c0;
            const int rb = rs ? rb1 : rb0;
#pragma unroll
            for (int t = 0; t < 8; t++) {
                float2 bv = *(const float2*)&s_b3[t * 8 + cw * 2];
                c[t][0] += bv.x; c[t][1] += bv.y;
                c[t][2] += bv.x; c[t][3] += bv.y;
            }
            float s0 = 0.0f, s1 = 0.0f;
#pragma unroll
            for (int t = 0; t < 8; t++) { s0 += c[t][0] + c[t][1]; s1 += c[t][2] + c[t][3]; }
            s0 += __shfl_xor_sync(0xffffffffu, s0, 1);
            s0 += __shfl_xor_sync(0xffffffffu, s0, 2);
            s1 += __shfl_xor_sync(0xffffffffu, s1, 1);
            s1 += __shfl_xor_sync(0xffffffffu, s1, 2);
            float m0 = s0 * (1.0f / 64.0f), m1 = s1 * (1.0f / 64.0f);
            float q0 = 0.0f, q1 = 0.0f;
#pragma unroll
            for (int t = 0; t < 8; t++) {
                float d0 = c[t][0] - m0, d1 = c[t][1] - m0;
                float d2 = c[t][2] - m1, d3 = c[t][3] - m1;
                q0 += d0 * d0 + d1 * d1;
                q1 += d2 * d2 + d3 * d3;
            }
            q0 += __shfl_xor_sync(0xffffffffu, q0, 1);
            q0 += __shfl_xor_sync(0xffffffffu, q0, 2);
            q1 += __shfl_xor_sync(0xffffffffu, q1, 1);
            q1 += __shfl_xor_sync(0xffffffffu, q1, 2);
            float i0 = rsqrtf(q0 * (1.0f / 64.0f) + 1e-5f);
            float i1 = rsqrtf(q1 * (1.0f / 64.0f) + 1e-5f);
            float* d0p = edge_out + (size_t)(bi * 256 + rb) * 64;
            float* d1p = d0p + 8 * 64;
#pragma unroll
            for (int t = 0; t < 8; t++) {
                int n = t * 8 + cw * 2;
                float2 gv = *(const float2*)&s_g[n];
                float2 bev = *(const float2*)&s_be[n];
                float2 o0, o1;
                o0.x = (c[t][0] - m0) * i0 * gv.x + bev.x;
                o0.y = (c[t][1] - m0) * i0 * gv.y + bev.y;
                o1.x = (c[t][2] - m1) * i1 * gv.x + bev.x;
                o1.y = (c[t][3] - m1) * i1 * gv.y + bev.y;
                *(float2*)&d0p[n] = o0;
                *(float2*)&d1p[n] = o1;
            }
        }
    }
}

// ================= Kernel 3: aggregation + node MLP + residual =================
// 256 threads: 64 cols x 4 i-partitions for the reduction, then 64-thread MLP.
__global__ __launch_bounds__(256) void k_agg_node(
    const int* __restrict__ atom, const float* __restrict__ mask,
    const float* __restrict__ na_w1, const float* __restrict__ na_b1,
    const float* __restrict__ na_w2, const float* __restrict__ na_b2,
    const float* __restrict__ na_w3, const float* __restrict__ na_b3,
    const float* __restrict__ na_g, const float* __restrict__ na_beta,
    const float* __restrict__ edge, float* __restrict__ node_out)
{
    int bj = blockIdx.x;
    int b = bj >> 8, j = bj & 255;
    int tid = threadIdx.x;
    int cc = tid & 63, p = tid >> 6;     // 64 cols x 4 i-partitions
    __shared__ float s_part[4][65], s_msum[4];
    __shared__ float s_x[128], s_h[64], s_h2[64], s_red[2], s_var[2];

    // 4-way parallel reduction over i
    float acc = 0.0f, msum = 0.0f;
    const float* ep = edge + ((size_t)(b * 65536 + j)) * 64 + (size_t)p * 64 * 16384 + cc;
    const float* mp = mask + b * 65536 + j + p * 64 * 256;
#pragma unroll 8
    for (int k = 0; k < 64; k++) {
        acc  += ep[(size_t)k * 16384];
        msum += mp[k * 256];
    }
    s_part[p][cc] = acc;
    if (cc == 0) s_msum[p] = msum;
    __syncthreads();

    if (tid < 64) {
        int c = tid;
        acc = s_part[0][c] + s_part[1][c] + s_part[2][c] + s_part[3][c];
        msum = s_msum[0] + s_msum[1] + s_msum[2] + s_msum[3];
        float gate = (atom[bj] >= 1) ? 1.0f : 0.0f;
        s_x[c]      = g_node[bj * 64 + c];
        s_x[64 + c] = acc / (msum + 1e-10f) * gate;
    }
    __syncthreads();

    float y = 0.0f;
    if (tid < 64) {
        int c = tid;
        y = na_b1[c];
#pragma unroll 8
        for (int k = 0; k < 128; k++) y += s_x[k] * na_w1[k * 64 + c];
        s_h[c] = fmaxf(y, 0.0f);
    }
    __syncthreads();
    if (tid < 64) {
        int c = tid;
        y = na_b2[c];
#pragma unroll 8
        for (int k = 0; k < 64; k++) y += s_h[k] * na_w2[k * 64 + c];
        s_h2[c] = fmaxf(y, 0.0f);
    }
    __syncthreads();
    if (tid < 64) {
        int c = tid;
        y = na_b3[c];
#pragma unroll 8
        for (int k = 0; k < 64; k++) y += s_h2[k] * na_w3[k * 64 + c];
        float v = y;
#pragma unroll
        for (int o = 16; o; o >>= 1) v += __shfl_xor_sync(0xffffffffu, v, o);
        if ((c & 31) == 0) s_red[c >> 5] = v;
    }
    __syncthreads();
    float mean = (s_red[0] + s_red[1]) * (1.0f / 64.0f);
    if (tid < 64) {
        int c = tid;
        float d = y - mean;
        float v = d * d;
#pragma unroll
        for (int o = 16; o; o >>= 1) v += __shfl_xor_sync(0xffffffffu, v, o);
        if ((c & 31) == 0) s_var[c >> 5] = v;
    }
    __syncthreads();
    if (tid < 64) {
        int c = tid;
        float var = (s_var[0] + s_var[1]) * (1.0f / 64.0f);
        float d = y - mean;
        node_out[bj * 64 + c] = s_x[c] + d * rsqrtf(var + 1e-5f) * na_g[c] + na_beta[c];
    }
}

// ================= launch =================
extern "C" void kernel_launch(void* const* d_in, const int* in_sizes, int n_in,
                              void* d_out, int out_size) {
    (void)in_sizes; (void)n_in; (void)out_size;
    const int*   atom    = (const int*)  d_in[0];
    const float* pos     = (const float*)d_in[1];
    const float* mask    = (const float*)d_in[2];
    const float* emb     = (const float*)d_in[3];
    const float* ne_w    = (const float*)d_in[4];
    const float* ne_b    = (const float*)d_in[5];
    const float* ne_g    = (const float*)d_in[6];
    const float* ne_beta = (const float*)d_in[7];
    const float* ee_w1   = (const float*)d_in[8];
    const float* ee_b1   = (const float*)d_in[9];
    const float* ee_w2   = (const float*)d_in[10];
    const float* ee_b2   = (const float*)d_in[11];
    const float* ee_w3   = (const float*)d_in[12];
    const float* ee_b3   = (const float*)d_in[13];
    const float* ee_g    = (const float*)d_in[14];
    const float* ee_beta = (const float*)d_in[15];
    const float* na_w1   = (const float*)d_in[16];
    const float* na_b1   = (const float*)d_in[17];
    const float* na_w2   = (const float*)d_in[18];
    const float* na_b2   = (const float*)d_in[19];
    const float* na_w3   = (const float*)d_in[20];
    const float* na_b3   = (const float*)d_in[21];
    const float* na_g    = (const float*)d_in[22];
    const float* na_beta = (const float*)d_in[23];

    float* out      = (float*)d_out;
    float* node_out = out;                  // (B,N,D)
    float* edge_out = out + PB * PN * 64;   // (B,N,N,E)

    const int SMEM_EDGE = SMEM_WORDS * 4;   // 163840 B
    cudaFuncSetAttribute(k_edge, cudaFuncAttributeMaxDynamicSharedMemorySize, SMEM_EDGE);

    k_node_prep<<<PB * PN / 4, dim3(64, 4)>>>(atom, emb, ne_w, ne_b, ne_g, ne_beta, ee_w1);
    k_wprep<<<1, 256>>>(ee_w1, ee_w2, ee_w3);
    k_edge<<<PB * PN, 256, SMEM_EDGE>>>(pos, mask, ee_b1, ee_b2, ee_b3,
                                        ee_g, ee_beta, edge_out);
    k_agg_node<<<PB * PN, 256>>>(atom, mask, na_w1, na_b1, na_w2, na_b2,
                                 na_w3, na_b3, na_g, na_beta, edge_out, node_out);
}

// round 14
// speedup vs baseline: 1.1043x; 1.1043x over previous
#include <cuda_runtime.h>
#include <cuda_bf16.h>
#include <math.h>
#include <stdint.h>

#define PB 8
#define PN 256

// ---------------- scratch ----------------
__device__ float g_node[PB * PN * 64];
__device__ float g_T[PB * PN * 64];
__device__ __align__(16) uint32_t g_node_h[PB * PN * 32];
__device__ __align__(16) uint32_t g_node_l[PB * PN * 32];
// fragment-ordered weights, vec4 interleaved: word = ((t*S+s)*32+lane)*4 + {h0,h1,l0,l1}
__device__ __align__(16) uint32_t g_wimg[14336];

#define W1_O 0          // S=6: 48*32*4 = 6144 words
#define W2_O 6144       // S=4: 32*32*4 = 4096
#define W3_O 10240      // S=4: 4096
#define WIMG_WORDS 14336

#define A_STR 52
#define AH_O  WIMG_WORDS
#define AL_O  (WIMG_WORDS + 128 * A_STR)
#define SMEM_WORDS (WIMG_WORDS + 2 * 128 * A_STR)   // 27648 words = 110592 B -> 2 blocks/SM

// res.lo = x0, res.hi = x1
#define PACK_BF16X2(res, x0, x1) \
    asm("cvt.rn.satfinite.bf16x2.f32 %0, %1, %2;" : "=r"(res) : "f"(x1), "f"(x0))

#define MMA_BF16(c, a, b0, b1) \
    asm volatile("mma.sync.aligned.m16n8k16.row.col.f32.bf16.bf16.f32 " \
        "{%0,%1,%2,%3}, {%4,%5,%6,%7}, {%8,%9}, {%0,%1,%2,%3};" \
        : "+f"((c)[0]), "+f"((c)[1]), "+f"((c)[2]), "+f"((c)[3]) \
        : "r"((a)[0]), "r"((a)[1]), "r"((a)[2]), "r"((a)[3]), "r"(b0), "r"(b1))

// exp(-x) for x >= 0, poly exp2 (no MUFU), rel err ~1.5e-4
__device__ __forceinline__ float fexp_neg(float x) {
    float y = -x * 1.44269504f;
    if (y < -126.0f) return 0.0f;
    float n = floorf(y);
    float f = y - n;
    float p = 1.0f + f * (0.6931472f + f * (0.2402265f + f * (0.0555041f +
              f * (0.0096181f + f * 0.0013333f))));
    return p * __int_as_float(((int)n + 127) << 23);
}

__device__ __forceinline__ void split_pack(float x0, float x1, uint32_t& h, uint32_t& l) {
    PACK_BF16X2(h, x0, x1);
    float e0 = x0 - __bfloat162float(__float2bfloat16_rn(x0));
    float e1 = x1 - __bfloat162float(__float2bfloat16_rn(x1));
    PACK_BF16X2(l, e0, e1);
}

// ================= Kernel 1: node embed + LN + T + bf16 hi/lo pack =================
__global__ __launch_bounds__(256) void k_node_prep(
    const int* __restrict__ atom, const float* __restrict__ emb,
    const float* __restrict__ ne_w, const float* __restrict__ ne_b,
    const float* __restrict__ ne_g, const float* __restrict__ ne_beta,
    const float* __restrict__ ee_w1)
{
    int y = threadIdx.y, c = threadIdx.x;
    int row = blockIdx.x * 4 + y;
    __shared__ float s_in[4][64], s_node[4][64], s_red[4][2];

    int a = atom[row];
    s_in[y][c] = fmaxf(emb[a * 64 + c], 0.0f);
    __syncthreads();

    float acc = ne_b[c];
#pragma unroll 8
    for (int k = 0; k < 64; k++) acc += s_in[y][k] * ne_w[k * 64 + c];

    float v = acc;
#pragma unroll
    for (int o = 16; o; o >>= 1) v += __shfl_xor_sync(0xffffffffu, v, o);
    if ((c & 31) == 0) s_red[y][c >> 5] = v;
    __syncthreads();
    float mean = (s_red[y][0] + s_red[y][1]) * (1.0f / 64.0f);
    float d = acc - mean;
    v = d * d;
#pragma unroll
    for (int o = 16; o; o >>= 1) v += __shfl_xor_sync(0xffffffffu, v, o);
    __syncthreads();
    if ((c & 31) == 0) s_red[y][c >> 5] = v;
    __syncthreads();
    float var = (s_red[y][0] + s_red[y][1]) * (1.0f / 64.0f);
    float nv = d * rsqrtf(var + 1e-5f) * ne_g[c] + ne_beta[c];

    g_node[row * 64 + c] = nv;
    s_node[y][c] = nv;
    __syncthreads();

    float tacc = 0.0f;
#pragma unroll 8
    for (int k = 0; k < 64; k++) tacc += s_node[y][k] * ee_w1[(64 + k) * 64 + c];
    g_T[row * 64 + c] = tacc;

    if (c < 32) {
        uint32_t hi, lo;
        split_pack(s_node[y][2 * c], s_node[y][2 * c + 1], hi, lo);
        g_node_h[row * 32 + c] = hi;
        g_node_l[row * 32 + c] = lo;
    }
}

// ================= Kernel 1b: fragment-ordered weight images (vec4) =================
// k = s*16 + (lane%4)*2 + reg*8 (w0=k, w1=k+1), n = t*8 + lane/4
__device__ __forceinline__ void wimg_put4(uint32_t* base, int ts, int lane, int reg,
                                          float w0, float w1) {
    uint32_t h, l;
    split_pack(w0, w1, h, l);
    base[(ts * 32 + lane) * 4 + reg]     = h;
    base[(ts * 32 + lane) * 4 + 2 + reg] = l;
}

__global__ __launch_bounds__(256) void k_wprep(
    const float* __restrict__ ee_w1, const float* __restrict__ ee_w2,
    const float* __restrict__ ee_w3)
{
    int tid = threadIdx.x;
    // Layer 1: S=6, K=96: k<32 -> Wr (ee_w1 rows 128..159), else Ws (rows 0..63)
    for (int idx = tid; idx < 3072; idx += 256) {
        int reg = idx & 1, lane = (idx >> 1) & 31, ts = idx >> 6;
        int s = ts % 6, t = ts / 6;
        int k = s * 16 + (lane & 3) * 2 + reg * 8;
        int n = t * 8 + (lane >> 2);
        float w0 = (k < 32)     ? ee_w1[(128 + k) * 64 + n] : ee_w1[(k - 32) * 64 + n];
        float w1 = (k + 1 < 32) ? ee_w1[(129 + k) * 64 + n] : ee_w1[(k - 31) * 64 + n];
        wimg_put4(&g_wimg[W1_O], ts, lane, reg, w0, w1);
    }
    // Layers 2/3: S=4, K=64
    for (int idx = tid; idx < 2048; idx += 256) {
        int reg = idx & 1, lane = (idx >> 1) & 31, ts = idx >> 6;
        int s = ts & 3, t = ts >> 2;
        int k = s * 16 + (lane & 3) * 2 + reg * 8;
        int n = t * 8 + (lane >> 2);
        wimg_put4(&g_wimg[W2_O], ts, lane, reg, ee_w2[k * 64 + n], ee_w2[(k + 1) * 64 + n]);
        wimg_put4(&g_wimg[W3_O], ts, lane, reg, ee_w3[k * 64 + n], ee_w3[(k + 1) * 64 + n]);
    }
}

// ---- one MLP layer, 16 rows per warp, vec4 B loads ----
template <int S>
__device__ __forceinline__ void do_layer(
    const uint32_t* __restrict__ sAh, const uint32_t* __restrict__ sAl,
    const uint32_t* __restrict__ w, int rb, int lane, float c[8][4])
{
    const int cw = lane & 3;
    uint32_t ah[S][4], al[S][4];
#pragma unroll
    for (int s = 0; s < S; s++) {
        const uint32_t* p = sAh + rb * A_STR + s * 8 + cw;
        const uint32_t* q = sAh + (rb + 8) * A_STR + s * 8 + cw;
        ah[s][0] = p[0]; ah[s][1] = q[0]; ah[s][2] = p[4]; ah[s][3] = q[4];
        p = sAl + rb * A_STR + s * 8 + cw;
        q = sAl + (rb + 8) * A_STR + s * 8 + cw;
        al[s][0] = p[0]; al[s][1] = q[0]; al[s][2] = p[4]; al[s][3] = q[4];
    }
#pragma unroll
    for (int t = 0; t < 8; t++) {
#pragma unroll
        for (int s = 0; s < S; s++) {
            uint4 bv = *(const uint4*)&w[((t * S + s) * 32 + lane) * 4];
            MMA_BF16(c[t], ah[s], bv.x, bv.y);
            MMA_BF16(c[t], al[s], bv.x, bv.y);
            MMA_BF16(c[t], ah[s], bv.z, bv.w);
        }
    }
}

// ---- epilogue: bias + relu + hi/lo split back into A buffer ----
__device__ __forceinline__ void epi_write(
    float c[8][4], const float* __restrict__ bias,
    uint32_t* __restrict__ sAh, uint32_t* __restrict__ sAl, int rb, int lane)
{
    uint32_t* w0h = sAh + rb * A_STR;
    uint32_t* w1h = sAh + (rb + 8) * A_STR;
    uint32_t* w0l = sAl + rb * A_STR;
    uint32_t* w1l = sAl + (rb + 8) * A_STR;
    const int cw = lane & 3;
#pragma unroll
    for (int t = 0; t < 8; t++) {
        float2 bv = *(const float2*)&bias[t * 8 + cw * 2];
        float x0 = fmaxf(c[t][0] + bv.x, 0.0f);
        float x1 = fmaxf(c[t][1] + bv.y, 0.0f);
        float x2 = fmaxf(c[t][2] + bv.x, 0.0f);
        float x3 = fmaxf(c[t][3] + bv.y, 0.0f);
        uint32_t h, l;
        split_pack(x0, x1, h, l);
        w0h[t * 4 + cw] = h; w0l[t * 4 + cw] = l;
        split_pack(x2, x3, h, l);
        w1h[t * 4 + cw] = h; w1l[t * 4 + cw] = l;
    }
}

// ================= Kernel 2: mma.sync edge MLP =================
// Block per (b,i), 256 threads (8 warps x 16 rows), 2 chunks of 128 j's.
__global__ __launch_bounds__(256) void k_edge(
    const float* __restrict__ pos, const float* __restrict__ mask,
    const float* __restrict__ ee_b1, const float* __restrict__ ee_b2,
    const float* __restrict__ ee_b3, const float* __restrict__ ee_g,
    const float* __restrict__ ee_beta, float* __restrict__ edge_out)
{
    extern __shared__ uint32_t sw[];
    __shared__ float s_Tp[64], s_b2[64], s_b3[64], s_g[64], s_be[64];

    const int tid = threadIdx.x;
    const int wid = tid >> 5;
    const int lane = tid & 31;
    const int bi = blockIdx.x;
    const int b = bi >> 8;

    // stage weight images once
    {
        const uint4* src = (const uint4*)g_wimg;
        uint4* dst = (uint4*)sw;
        for (int i = tid; i < WIMG_WORDS / 4; i += 256) dst[i] = src[i];
    }
    if (tid < 64) {
        s_Tp[tid] = g_T[bi * 64 + tid] + ee_b1[tid];
        s_b2[tid] = ee_b2[tid];
        s_b3[tid] = ee_b3[tid];
        s_g[tid]  = ee_g[tid];
        s_be[tid] = ee_beta[tid];
    }

    uint32_t* sAh = sw + AH_O;
    uint32_t* sAl = sw + AL_O;

    const float px = pos[bi * 3 + 0];
    const float py = pos[bi * 3 + 1];
    const float pz = pos[bi * 3 + 2];

    const int rb = wid * 16 + (lane >> 2);   // rows rb, rb+8
    const int cw = lane & 3;

    for (int jc = 0; jc < 2; jc++) {
        const int j0 = jc * 128;
        __syncthreads();  // weights staged / previous chunk fully consumed

        // ---- build A1 = [rbf(32) | node(64)] for rows 0..127 ----
        if (tid < 128) {
            const int row = tid;
            const int gj = b * 256 + j0 + row;
            float qx = pos[gj * 3 + 0], qy = pos[gj * 3 + 1], qz = pos[gj * 3 + 2];
            float mk = mask[bi * 256 + j0 + row];
            float dx = px - qx, dy = py - qy, dz = pz - qz;
            float dist = sqrtf(dx * dx + dy * dy + dz * dz + 1e-10f) * mk;
            uint32_t* rh = sAh + row * A_STR;
            uint32_t* rl = sAl + row * A_STR;
#pragma unroll
            for (int w = 0; w < 16; w++) {
                float t0 = (dist - (20.0f / 31.0f) * (float)(2 * w)) * 1.6f;
                float t1 = (dist - (20.0f / 31.0f) * (float)(2 * w + 1)) * 1.6f;
                float x0 = fexp_neg(t0 * t0) * mk;
                float x1 = fexp_neg(t1 * t1) * mk;
                uint32_t h, l;
                split_pack(x0, x1, h, l);
                rh[w] = h; rl[w] = l;
            }
            const uint4* nh = (const uint4*)(g_node_h + gj * 32);
            const uint4* nl = (const uint4*)(g_node_l + gj * 32);
#pragma unroll
            for (int q = 0; q < 8; q++) {
                *(uint4*)&rh[16 + 4 * q] = nh[q];
                *(uint4*)&rl[16 + 4 * q] = nl[q];
            }
        }
        __syncthreads();

        // ---- layer 1 (K=96) ----
        {
            float c[8][4] = {};
            do_layer<6>(sAh, sAl, sw + W1_O, rb, lane, c);
            epi_write(c, s_Tp, sAh, sAl, rb, lane);
        }
        __syncwarp();
        // ---- layer 2 (K=64) ----
        {
            float c[8][4] = {};
            do_layer<4>(sAh, sAl, sw + W2_O, rb, lane, c);
            epi_write(c, s_b2, sAh, sAl, rb, lane);
        }
        __syncwarp();
        // ---- layer 3 (K=64) + LayerNorm + store ----
        {
            float c[8][4] = {};
            do_layer<4>(sAh, sAl, sw + W3_O, rb, lane, c);
#pragma unroll
            for (int t = 0; t < 8; t++) {
                float2 bv = *(const float2*)&s_b3[t * 8 + cw * 2];
                c[t][0] += bv.x; c[t][1] += bv.y;
                c[t][2] += bv.x; c[t][3] += bv.y;
            }
            float s0 = 0.0f, s1 = 0.0f;
#pragma unroll
            for (int t = 0; t < 8; t++) { s0 += c[t][0] + c[t][1]; s1 += c[t][2] + c[t][3]; }
            s0 += __shfl_xor_sync(0xffffffffu, s0, 1);
            s0 += __shfl_xor_sync(0xffffffffu, s0, 2);
            s1 += __shfl_xor_sync(0xffffffffu, s1, 1);
            s1 += __shfl_xor_sync(0xffffffffu, s1, 2);
            float m0 = s0 * (1.0f / 64.0f), m1 = s1 * (1.0f / 64.0f);
            float q0 = 0.0f, q1 = 0.0f;
#pragma unroll
            for (int t = 0; t < 8; t++) {
                float d0 = c[t][0] - m0, d1 = c[t][1] - m0;
                float d2 = c[t][2] - m1, d3 = c[t][3] - m1;
                q0 += d0 * d0 + d1 * d1;
                q1 += d2 * d2 + d3 * d3;
            }
            q0 += __shfl_xor_sync(0xffffffffu, q0, 1);
            q0 += __shfl_xor_sync(0xffffffffu, q0, 2);
            q1 += __shfl_xor_sync(0xffffffffu, q1, 1);
            q1 += __shfl_xor_sync(0xffffffffu, q1, 2);
            float i0 = rsqrtf(q0 * (1.0f / 64.0f) + 1e-5f);
            float i1 = rsqrtf(q1 * (1.0f / 64.0f) + 1e-5f);
            float* d0p = edge_out + (size_t)(bi * 256 + j0 + rb) * 64;
            float* d1p = d0p + 8 * 64;
#pragma unroll
            for (int t = 0; t < 8; t++) {
                int n = t * 8 + cw * 2;
                float2 gv = *(const float2*)&s_g[n];
                float2 bev = *(const float2*)&s_be[n];
                float2 o0, o1;
                o0.x = (c[t][0] - m0) * i0 * gv.x + bev.x;
                o0.y = (c[t][1] - m0) * i0 * gv.y + bev.y;
                o1.x = (c[t][2] - m1) * i1 * gv.x + bev.x;
                o1.y = (c[t][3] - m1) * i1 * gv.y + bev.y;
                *(float2*)&d0p[n] = o0;
                *(float2*)&d1p[n] = o1;
            }
        }
    }
}

// ================= Kernel 3: aggregation + node MLP + residual =================
// 256 threads = 16 c-quads x 16 i-partitions; float4 loads for deep MLP.
__global__ __launch_bounds__(256) void k_agg_node(
    const int* __restrict__ atom, const float* __restrict__ mask,
    const float* __restrict__ na_w1, const float* __restrict__ na_b1,
    const float* __restrict__ na_w2, const float* __restrict__ na_b2,
    const float* __restrict__ na_w3, const float* __restrict__ na_b3,
    const float* __restrict__ na_g, const float* __restrict__ na_beta,
    const float* __restrict__ edge, float* __restrict__ node_out)
{
    int bj = blockIdx.x;
    int b = bj >> 8, j = bj & 255;
    int tid = threadIdx.x;
    int cq = tid & 15;       // c-quad: cols cq*4..cq*4+3
    int p  = tid >> 4;       // i-partition 0..15 (i = p*16..p*16+15)
    __shared__ float s_part[16][68];
    __shared__ float s_msum[16];
    __shared__ float s_x[128], s_h[64], s_h2[64], s_red[2], s_var[2];

    // 16-way parallel reduction over i, float4 per thread (16 loads in flight)
    {
        const float4* ep = (const float4*)(edge + ((size_t)b * 65536 + j) * 64) + cq;
        float4 a = make_float4(0.f, 0.f, 0.f, 0.f);
#pragma unroll
        for (int k = 0; k < 16; k++) {
            float4 v = ep[(size_t)(p * 16 + k) * 4096];   // i stride = 256*64 floats
            a.x += v.x; a.y += v.y; a.z += v.z; a.w += v.w;
        }
        *(float4*)&s_part[p][cq * 4] = a;
        if (cq == 0) {
            const float* mp = mask + b * 65536 + j + p * 16 * 256;
            float ms = 0.0f;
#pragma unroll
            for (int k = 0; k < 16; k++) ms += mp[k * 256];
            s_msum[p] = ms;
        }
    }
    __syncthreads();

    if (tid < 64) {
        int c = tid;
        float acc = 0.0f;
#pragma unroll
        for (int q = 0; q < 16; q++) acc += s_part[q][c];
        float msum = 0.0f;
#pragma unroll
        for (int q = 0; q < 16; q++) msum += s_msum[q];
        float gate = (atom[bj] >= 1) ? 1.0f : 0.0f;
        s_x[c]      = g_node[bj * 64 + c];
        s_x[64 + c] = acc / (msum + 1e-10f) * gate;
    }
    __syncthreads();

    float y = 0.0f;
    if (tid < 64) {
        int c = tid;
        y = na_b1[c];
#pragma unroll 8
        for (int k = 0; k < 128; k++) y += s_x[k] * na_w1[k * 64 + c];
        s_h[c] = fmaxf(y, 0.0f);
    }
    __syncthreads();
    if (tid < 64) {
        int c = tid;
        y = na_b2[c];
#pragma unroll 8
        for (int k = 0; k < 64; k++) y += s_h[k] * na_w2[k * 64 + c];
        s_h2[c] = fmaxf(y, 0.0f);
    }
    __syncthreads();
    if (tid < 64) {
        int c = tid;
        y = na_b3[c];
#pragma unroll 8
        for (int k = 0; k < 64; k++) y += s_h2[k] * na_w3[k * 64 + c];
        float v = y;
#pragma unroll
        for (int o = 16; o; o >>= 1) v += __shfl_xor_sync(0xffffffffu, v, o);
        if ((c & 31) == 0) s_red[c >> 5] = v;
    }
    __syncthreads();
    float mean = (s_red[0] + s_red[1]) * (1.0f / 64.0f);
    if (tid < 64) {
        int c = tid;
        float d = y - mean;
        float v = d * d;
#pragma unroll
        for (int o = 16; o; o >>= 1) v += __shfl_xor_sync(0xffffffffu, v, o);
        if ((c & 31) == 0) s_var[c >> 5] = v;
    }
    __syncthreads();
    if (tid < 64) {
        int c = tid;
        float var = (s_var[0] + s_var[1]) * (1.0f / 64.0f);
        float d = y - mean;
        node_out[bj * 64 + c] = s_x[c] + d * rsqrtf(var + 1e-5f) * na_g[c] + na_beta[c];
    }
}

// ================= launch =================
extern "C" void kernel_launch(void* const* d_in, const int* in_sizes, int n_in,
                              void* d_out, int out_size) {
    (void)in_sizes; (void)n_in; (void)out_size;
    const int*   atom    = (const int*)  d_in[0];
    const float* pos     = (const float*)d_in[1];
    const float* mask    = (const float*)d_in[2];
    const float* emb     = (const float*)d_in[3];
    const float* ne_w    = (const float*)d_in[4];
    const float* ne_b    = (const float*)d_in[5];
    const float* ne_g    = (const float*)d_in[6];
    const float* ne_beta = (const float*)d_in[7];
    const float* ee_w1   = (const float*)d_in[8];
    const float* ee_b1   = (const float*)d_in[9];
    const float* ee_w2   = (const float*)d_in[10];
    const float* ee_b2   = (const float*)d_in[11];
    const float* ee_w3   = (const float*)d_in[12];
    const float* ee_b3   = (const float*)d_in[13];
    const float* ee_g    = (const float*)d_in[14];
    const float* ee_beta = (const float*)d_in[15];
    const float* na_w1   = (const float*)d_in[16];
    const float* na_b1   = (const float*)d_in[17];
    const float* na_w2   = (const float*)d_in[18];
    const float* na_b2   = (const float*)d_in[19];
    const float* na_w3   = (const float*)d_in[20];
    const float* na_b3   = (const float*)d_in[21];
    const float* na_g    = (const float*)d_in[22];
    const float* na_beta = (const float*)d_in[23];

    float* out      = (float*)d_out;
    float* node_out = out;                  // (B,N,D)
    float* edge_out = out + PB * PN * 64;   // (B,N,N,E)

    const int SMEM_EDGE = SMEM_WORDS * 4;   // 110592 B
    cudaFuncSetAttribute(k_edge, cudaFuncAttributeMaxDynamicSharedMemorySize, SMEM_EDGE);

    k_node_prep<<<PB * PN / 4, dim3(64, 4)>>>(atom, emb, ne_w, ne_b, ne_g, ne_beta, ee_w1);
    k_wprep<<<1, 256>>>(ee_w1, ee_w2, ee_w3);
    k_edge<<<PB * PN, 256, SMEM_EDGE>>>(pos, mask, ee_b1, ee_b2, ee_b3,
                                        ee_g, ee_beta, edge_out);
    k_agg_node<<<PB * PN, 256>>>(atom, mask, na_w1, na_b1, na_w2, na_b2,
                                 na_w3, na_b3, na_g, na_beta, edge_out, node_out);
}

// round 16
// speedup vs baseline: 1.3340x; 1.2079x over previous
#include <cuda_runtime.h>
#include <cuda_bf16.h>
#include <math.h>
#include <stdint.h>

#define PB 8
#define PN 256

// ---------------- scratch ----------------
__device__ float g_node[PB * PN * 64];
__device__ float g_T[PB * PN * 64];
__device__ __align__(16) uint32_t g_node_h[PB * PN * 32];
__device__ __align__(16) uint32_t g_node_l[PB * PN * 32];
// fragment-ordered weights, vec4 interleaved: word = ((t*S+s)*32+lane)*4 + {h0,h1,l0,l1}
__device__ __align__(16) uint32_t g_wimg[14336];
// agg partials: 32 i-groups x 8 b x (256 j x 64 c)
__device__ __align__(16) float g_part[256 * 16384];
__device__ float m_part[256 * 256];

#define W1_O 0          // S=6: 48*32*4 = 6144 words
#define W2_O 6144       // S=4: 32*32*4 = 4096
#define W3_O 10240      // S=4: 4096
#define WIMG_WORDS 14336

// res.lo = x0, res.hi = x1
#define PACK_BF16X2(res, x0, x1) \
    asm("cvt.rn.satfinite.bf16x2.f32 %0, %1, %2;" : "=r"(res) : "f"(x1), "f"(x0))

#define MMA_BF16(c, a, b0, b1) \
    asm volatile("mma.sync.aligned.m16n8k16.row.col.f32.bf16.bf16.f32 " \
        "{%0,%1,%2,%3}, {%4,%5,%6,%7}, {%8,%9}, {%0,%1,%2,%3};" \
        : "+f"((c)[0]), "+f"((c)[1]), "+f"((c)[2]), "+f"((c)[3]) \
        : "r"((a)[0]), "r"((a)[1]), "r"((a)[2]), "r"((a)[3]), "r"(b0), "r"(b1))

// exp(-x) for x >= 0, poly exp2 (no MUFU), rel err ~1.5e-4
__device__ __forceinline__ float fexp_neg(float x) {
    float y = -x * 1.44269504f;
    if (y < -126.0f) return 0.0f;
    float n = floorf(y);
    float f = y - n;
    float p = 1.0f + f * (0.6931472f + f * (0.2402265f + f * (0.0555041f +
              f * (0.0096181f + f * 0.0013333f))));
    return p * __int_as_float(((int)n + 127) << 23);
}

__device__ __forceinline__ void split_pack(float x0, float x1, uint32_t& h, uint32_t& l) {
    PACK_BF16X2(h, x0, x1);
    float e0 = x0 - __bfloat162float(__float2bfloat16_rn(x0));
    float e1 = x1 - __bfloat162float(__float2bfloat16_rn(x1));
    PACK_BF16X2(l, e0, e1);
}

// ================= Kernel 1: node embed + LN + T + bf16 hi/lo pack =================
__global__ __launch_bounds__(256) void k_node_prep(
    const int* __restrict__ atom, const float* __restrict__ emb,
    const float* __restrict__ ne_w, const float* __restrict__ ne_b,
    const float* __restrict__ ne_g, const float* __restrict__ ne_beta,
    const float* __restrict__ ee_w1)
{
    int y = threadIdx.y, c = threadIdx.x;
    int row = blockIdx.x * 4 + y;
    __shared__ float s_in[4][64], s_node[4][64], s_red[4][2];

    int a = atom[row];
    s_in[y][c] = fmaxf(emb[a * 64 + c], 0.0f);
    __syncthreads();

    float acc = ne_b[c];
#pragma unroll 8
    for (int k = 0; k < 64; k++) acc += s_in[y][k] * ne_w[k * 64 + c];

    float v = acc;
#pragma unroll
    for (int o = 16; o; o >>= 1) v += __shfl_xor_sync(0xffffffffu, v, o);
    if ((c & 31) == 0) s_red[y][c >> 5] = v;
    __syncthreads();
    float mean = (s_red[y][0] + s_red[y][1]) * (1.0f / 64.0f);
    float d = acc - mean;
    v = d * d;
#pragma unroll
    for (int o = 16; o; o >>= 1) v += __shfl_xor_sync(0xffffffffu, v, o);
    __syncthreads();
    if ((c & 31) == 0) s_red[y][c >> 5] = v;
    __syncthreads();
    float var = (s_red[y][0] + s_red[y][1]) * (1.0f / 64.0f);
    float nv = d * rsqrtf(var + 1e-5f) * ne_g[c] + ne_beta[c];

    g_node[row * 64 + c] = nv;
    s_node[y][c] = nv;
    __syncthreads();

    float tacc = 0.0f;
#pragma unroll 8
    for (int k = 0; k < 64; k++) tacc += s_node[y][k] * ee_w1[(64 + k) * 64 + c];
    g_T[row * 64 + c] = tacc;

    if (c < 32) {
        uint32_t hi, lo;
        split_pack(s_node[y][2 * c], s_node[y][2 * c + 1], hi, lo);
        g_node_h[row * 32 + c] = hi;
        g_node_l[row * 32 + c] = lo;
    }
}

// ================= Kernel 1b: fragment-ordered weight images (vec4) =================
__device__ __forceinline__ void wimg_put4(uint32_t* base, int ts, int lane, int reg,
                                          float w0, float w1) {
    uint32_t h, l;
    split_pack(w0, w1, h, l);
    base[(ts * 32 + lane) * 4 + reg]     = h;
    base[(ts * 32 + lane) * 4 + 2 + reg] = l;
}

__global__ __launch_bounds__(256) void k_wprep(
    const float* __restrict__ ee_w1, const float* __restrict__ ee_w2,
    const float* __restrict__ ee_w3)
{
    int tid = threadIdx.x;
    // Layer 1: S=6, K=96: k<32 -> Wr (ee_w1 rows 128..159), else Ws (rows 0..63)
    for (int idx = tid; idx < 3072; idx += 256) {
        int reg = idx & 1, lane = (idx >> 1) & 31, ts = idx >> 6;
        int s = ts % 6, t = ts / 6;
        int k = s * 16 + (lane & 3) * 2 + reg * 8;
        int n = t * 8 + (lane >> 2);
        float w0 = (k < 32)     ? ee_w1[(128 + k) * 64 + n] : ee_w1[(k - 32) * 64 + n];
        float w1 = (k + 1 < 32) ? ee_w1[(129 + k) * 64 + n] : ee_w1[(k - 31) * 64 + n];
        wimg_put4(&g_wimg[W1_O], ts, lane, reg, w0, w1);
    }
    // Layers 2/3: S=4, K=64
    for (int idx = tid; idx < 2048; idx += 256) {
        int reg = idx & 1, lane = (idx >> 1) & 31, ts = idx >> 6;
        int s = ts & 3, t = ts >> 2;
        int k = s * 16 + (lane & 3) * 2 + reg * 8;
        int n = t * 8 + (lane >> 2);
        wimg_put4(&g_wimg[W2_O], ts, lane, reg, ee_w2[k * 64 + n], ee_w2[(k + 1) * 64 + n]);
        wimg_put4(&g_wimg[W3_O], ts, lane, reg, ee_w3[k * 64 + n], ee_w3[(k + 1) * 64 + n]);
    }
}

// rbf pair for cols k, k+1 -> packed hi/lo
__device__ __forceinline__ void rbf_pair(float dist, float mk, int k,
                                         uint32_t& h, uint32_t& l) {
    float t0 = (dist - (20.0f / 31.0f) * (float)k) * 1.6f;
    float t1 = (dist - (20.0f / 31.0f) * (float)(k + 1)) * 1.6f;
    float x0 = fexp_neg(t0 * t0) * mk;
    float x1 = fexp_neg(t1 * t1) * mk;
    split_pack(x0, x1, h, l);
}

// bias+relu+split: C frags -> next layer A frags (all registers)
__device__ __forceinline__ void xform(
    float c[8][4], const float* __restrict__ bias, int cw,
    uint32_t h0[8], uint32_t h1[8], uint32_t l0[8], uint32_t l1[8])
{
#pragma unroll
    for (int t = 0; t < 8; t++) {
        float2 bv = *(const float2*)&bias[t * 8 + cw * 2];
        float x0 = fmaxf(c[t][0] + bv.x, 0.0f);
        float x1 = fmaxf(c[t][1] + bv.y, 0.0f);
        float x2 = fmaxf(c[t][2] + bv.x, 0.0f);
        float x3 = fmaxf(c[t][3] + bv.y, 0.0f);
        split_pack(x0, x1, h0[t], l0[t]);
        split_pack(x2, x3, h1[t], l1[t]);
    }
}

// ================= Kernel 2: register-chained mma.sync edge MLP =================
// Block per (b,i), 256 threads, 2 chunks of 128 j's. Warp owns 16 rows; all
// activations live in registers (C-frag layout == next A-frag layout).
__global__ __launch_bounds__(256, 2) void k_edge(
    const float* __restrict__ pos, const float* __restrict__ mask,
    const float* __restrict__ ee_b1, const float* __restrict__ ee_b2,
    const float* __restrict__ ee_b3, const float* __restrict__ ee_g,
    const float* __restrict__ ee_beta, float* __restrict__ edge_out)
{
    extern __shared__ uint32_t sw[];   // weight image only (57344 B)
    __shared__ float s_Tp[64], s_b2[64], s_b3[64], s_g[64], s_be[64];

    const int tid = threadIdx.x;
    const int wid = tid >> 5;
    const int lane = tid & 31;
    const int q = lane >> 2;
    const int cw = lane & 3;
    const int bi = blockIdx.x;
    const int b = bi >> 8;

    {
        const uint4* src = (const uint4*)g_wimg;
        uint4* dst = (uint4*)sw;
        for (int i = tid; i < WIMG_WORDS / 4; i += 256) dst[i] = src[i];
    }
    if (tid < 64) {
        s_Tp[tid] = g_T[bi * 64 + tid] + ee_b1[tid];
        s_b2[tid] = ee_b2[tid];
        s_b3[tid] = ee_b3[tid];
        s_g[tid]  = ee_g[tid];
        s_be[tid] = ee_beta[tid];
    }
    __syncthreads();

    const float px = pos[bi * 3 + 0];
    const float py = pos[bi * 3 + 1];
    const float pz = pos[bi * 3 + 2];

#pragma unroll 1
    for (int jc = 0; jc < 2; jc++) {
        const int r0 = jc * 128 + wid * 16 + q;   // local j of rowset 0 (rowset 1 = +8)
        const int gj0 = b * 256 + r0;
        const int gj1 = gj0 + 8;

        // distances for this thread's two rows
        float d0, mk0, d1, mk1;
        {
            float qx = pos[gj0 * 3 + 0], qy = pos[gj0 * 3 + 1], qz = pos[gj0 * 3 + 2];
            mk0 = mask[bi * 256 + r0];
            float dx = px - qx, dy = py - qy, dz = pz - qz;
            d0 = sqrtf(dx * dx + dy * dy + dz * dz + 1e-10f) * mk0;
            qx = pos[gj1 * 3 + 0]; qy = pos[gj1 * 3 + 1]; qz = pos[gj1 * 3 + 2];
            mk1 = mask[bi * 256 + r0 + 8];
            dx = px - qx; dy = py - qy; dz = pz - qz;
            d1 = sqrtf(dx * dx + dy * dy + dz * dz + 1e-10f) * mk1;
        }

        float c[8][4] = {};

        // ---- layer 1 (K=96): A frags built per-thread ----
#pragma unroll
        for (int s = 0; s < 6; s++) {
            uint32_t ah[4], al[4];
            if (s < 2) {
                int k = s * 16 + cw * 2;
                rbf_pair(d0, mk0, k,     ah[0], al[0]);
                rbf_pair(d1, mk1, k,     ah[1], al[1]);
                rbf_pair(d0, mk0, k + 8, ah[2], al[2]);
                rbf_pair(d1, mk1, k + 8, ah[3], al[3]);
            } else {
                int w0 = gj0 * 32 + (s - 2) * 8 + cw;
                int w1 = gj1 * 32 + (s - 2) * 8 + cw;
                ah[0] = g_node_h[w0];     ah[1] = g_node_h[w1];
                ah[2] = g_node_h[w0 + 4]; ah[3] = g_node_h[w1 + 4];
                al[0] = g_node_l[w0];     al[1] = g_node_l[w1];
                al[2] = g_node_l[w0 + 4]; al[3] = g_node_l[w1 + 4];
            }
#pragma unroll
            for (int t = 0; t < 8; t++) {
                uint4 bv = *(const uint4*)&sw[W1_O + ((t * 6 + s) * 32 + lane) * 4];
                MMA_BF16(c[t], ah, bv.x, bv.y);
                MMA_BF16(c[t], al, bv.x, bv.y);
                MMA_BF16(c[t], ah, bv.z, bv.w);
            }
        }

        uint32_t h0[8], h1[8], l0[8], l1[8];
        xform(c, s_Tp, cw, h0, h1, l0, l1);

        // ---- layer 2 (K=64) ----
#pragma unroll
        for (int t = 0; t < 8; t++) { c[t][0] = 0.f; c[t][1] = 0.f; c[t][2] = 0.f; c[t][3] = 0.f; }
#pragma unroll
        for (int s = 0; s < 4; s++) {
            uint32_t ah[4] = {h0[2 * s], h1[2 * s], h0[2 * s + 1], h1[2 * s + 1]};
            uint32_t al[4] = {l0[2 * s], l1[2 * s], l0[2 * s + 1], l1[2 * s + 1]};
#pragma unroll
            for (int t = 0; t < 8; t++) {
                uint4 bv = *(const uint4*)&sw[W2_O + ((t * 4 + s) * 32 + lane) * 4];
                MMA_BF16(c[t], ah, bv.x, bv.y);
                MMA_BF16(c[t], al, bv.x, bv.y);
                MMA_BF16(c[t], ah, bv.z, bv.w);
            }
        }
        xform(c, s_b2, cw, h0, h1, l0, l1);

        // ---- layer 3 (K=64) ----
#pragma unroll
        for (int t = 0; t < 8; t++) { c[t][0] = 0.f; c[t][1] = 0.f; c[t][2] = 0.f; c[t][3] = 0.f; }
#pragma unroll
        for (int s = 0; s < 4; s++) {
            uint32_t ah[4] = {h0[2 * s], h1[2 * s], h0[2 * s + 1], h1[2 * s + 1]};
            uint32_t al[4] = {l0[2 * s], l1[2 * s], l0[2 * s + 1], l1[2 * s + 1]};
#pragma unroll
            for (int t = 0; t < 8; t++) {
                uint4 bv = *(const uint4*)&sw[W3_O + ((t * 4 + s) * 32 + lane) * 4];
                MMA_BF16(c[t], ah, bv.x, bv.y);
                MMA_BF16(c[t], al, bv.x, bv.y);
                MMA_BF16(c[t], ah, bv.z, bv.w);
            }
        }

        // ---- bias + LayerNorm + store ----
#pragma unroll
        for (int t = 0; t < 8; t++) {
            float2 bv = *(const float2*)&s_b3[t * 8 + cw * 2];
            c[t][0] += bv.x; c[t][1] += bv.y;
            c[t][2] += bv.x; c[t][3] += bv.y;
        }
        float s0 = 0.0f, s1 = 0.0f;
#pragma unroll
        for (int t = 0; t < 8; t++) { s0 += c[t][0] + c[t][1]; s1 += c[t][2] + c[t][3]; }
        s0 += __shfl_xor_sync(0xffffffffu, s0, 1);
        s0 += __shfl_xor_sync(0xffffffffu, s0, 2);
        s1 += __shfl_xor_sync(0xffffffffu, s1, 1);
        s1 += __shfl_xor_sync(0xffffffffu, s1, 2);
        float m0 = s0 * (1.0f / 64.0f), m1 = s1 * (1.0f / 64.0f);
        float q0 = 0.0f, q1 = 0.0f;
#pragma unroll
        for (int t = 0; t < 8; t++) {
            float e0 = c[t][0] - m0, e1 = c[t][1] - m0;
            float e2 = c[t][2] - m1, e3 = c[t][3] - m1;
            q0 += e0 * e0 + e1 * e1;
            q1 += e2 * e2 + e3 * e3;
        }
        q0 += __shfl_xor_sync(0xffffffffu, q0, 1);
        q0 += __shfl_xor_sync(0xffffffffu, q0, 2);
        q1 += __shfl_xor_sync(0xffffffffu, q1, 1);
        q1 += __shfl_xor_sync(0xffffffffu, q1, 2);
        float i0 = rsqrtf(q0 * (1.0f / 64.0f) + 1e-5f);
        float i1 = rsqrtf(q1 * (1.0f / 64.0f) + 1e-5f);
        float* d0p = edge_out + (size_t)(bi * 256 + r0) * 64;
        float* d1p = d0p + 8 * 64;
#pragma unroll
        for (int t = 0; t < 8; t++) {
            int n = t * 8 + cw * 2;
            float2 gv = *(const float2*)&s_g[n];
            float2 bev = *(const float2*)&s_be[n];
            float2 o0, o1;
            o0.x = (c[t][0] - m0) * i0 * gv.x + bev.x;
            o0.y = (c[t][1] - m0) * i0 * gv.y + bev.y;
            o1.x = (c[t][2] - m1) * i1 * gv.x + bev.x;
            o1.y = (c[t][3] - m1) * i1 * gv.y + bev.y;
            *(float2*)&d0p[n] = o0;
            *(float2*)&d1p[n] = o1;
        }
    }
}

// ================= Kernel 3a: contiguous partial aggregation =================
// Block per (b, p): p = i-group of 8. Streams 8 contiguous 64KB (j,c) planes,
// accumulates in 64 regs, writes one contiguous 64KB partial.
__global__ __launch_bounds__(256) void k_agg1(
    const float* __restrict__ edge, const float* __restrict__ mask)
{
    int bp = blockIdx.x;
    int b = bp >> 5, p = bp & 31;
    int tid = threadIdx.x;

    float4 acc[16];
#pragma unroll
    for (int s = 0; s < 16; s++) acc[s] = make_float4(0.f, 0.f, 0.f, 0.f);

    const float4* base = (const float4*)(edge + (size_t)(b * 256 + p * 8) * 16384);
#pragma unroll 1
    for (int i = 0; i < 8; i++) {
        const float4* pl = base + (size_t)i * 4096;
#pragma unroll
        for (int s = 0; s < 16; s++) {
            float4 v = pl[s * 256 + tid];
            acc[s].x += v.x; acc[s].y += v.y; acc[s].z += v.z; acc[s].w += v.w;
        }
    }
    float4* out = (float4*)(g_part + (size_t)bp * 16384);
#pragma unroll
    for (int s = 0; s < 16; s++) out[s * 256 + tid] = acc[s];

    // mask partial: thread = j
    float ms = 0.0f;
    const float* mp = mask + b * 65536 + p * 8 * 256 + tid;
#pragma unroll
    for (int i = 0; i < 8; i++) ms += mp[i * 256];
    m_part[bp * 256 + tid] = ms;
}

// ================= Kernel 3b: partial reduce + node MLP + residual =================
__global__ __launch_bounds__(256) void k_agg_node(
    const int* __restrict__ atom,
    const float* __restrict__ na_w1, const float* __restrict__ na_b1,
    const float* __restrict__ na_w2, const float* __restrict__ na_b2,
    const float* __restrict__ na_w3, const float* __restrict__ na_b3,
    const float* __restrict__ na_g, const float* __restrict__ na_beta,
    float* __restrict__ node_out)
{
    int bj = blockIdx.x;
    int b = bj >> 8, j = bj & 255;
    int tid = threadIdx.x;
    int cq = tid & 15, pt = tid >> 4;    // 16 cq x 16 pt
    __shared__ float s_part[16][68];
    __shared__ float s_x[128], s_h[64], s_h2[64], s_red[2], s_var[2], s_ms[1];

    // reduce 32 partials: each (pt) handles p = pt and pt+16
    {
        const float* g0 = g_part + (size_t)(b * 32 + pt) * 16384 + j * 64 + cq * 4;
        const float* g1 = g0 + (size_t)16 * 16384;
        float4 v0 = *(const float4*)g0;
        float4 v1 = *(const float4*)g1;
        v0.x += v1.x; v0.y += v1.y; v0.z += v1.z; v0.w += v1.w;
        *(float4*)&s_part[pt][cq * 4] = v0;
    }
    if (tid < 32) {
        float ms = m_part[(b * 32 + tid) * 256 + j];
#pragma unroll
        for (int o = 16; o; o >>= 1) ms += __shfl_xor_sync(0xffffffffu, ms, o);
        if (tid == 0) s_ms[0] = ms;
    }
    __syncthreads();

    if (tid < 64) {
        int c = tid;
        float acc = 0.0f;
#pragma unroll
        for (int t = 0; t < 16; t++) acc += s_part[t][c];
        float gate = (atom[bj] >= 1) ? 1.0f : 0.0f;
        s_x[c]      = g_node[bj * 64 + c];
        s_x[64 + c] = acc / (s_ms[0] + 1e-10f) * gate;
    }
    __syncthreads();

    float y = 0.0f;
    if (tid < 64) {
        int c = tid;
        y = na_b1[c];
#pragma unroll 8
        for (int k = 0; k < 128; k++) y += s_x[k] * na_w1[k * 64 + c];
        s_h[c] = fmaxf(y, 0.0f);
    }
    __syncthreads();
    if (tid < 64) {
        int c = tid;
        y = na_b2[c];
#pragma unroll 8
        for (int k = 0; k < 64; k++) y += s_h[k] * na_w2[k * 64 + c];
        s_h2[c] = fmaxf(y, 0.0f);
    }
    __syncthreads();
    if (tid < 64) {
        int c = tid;
        y = na_b3[c];
#pragma unroll 8
        for (int k = 0; k < 64; k++) y += s_h2[k] * na_w3[k * 64 + c];
        float v = y;
#pragma unroll
        for (int o = 16; o; o >>= 1) v += __shfl_xor_sync(0xffffffffu, v, o);
        if ((c & 31) == 0) s_red[c >> 5] = v;
    }
    __syncthreads();
    float mean = (s_red[0] + s_red[1]) * (1.0f / 64.0f);
    if (tid < 64) {
        int c = tid;
        float d = y - mean;
        float v = d * d;
#pragma unroll
        for (int o = 16; o; o >>= 1) v += __shfl_xor_sync(0xffffffffu, v, o);
        if ((c & 31) == 0) s_var[c >> 5] = v;
    }
    __syncthreads();
    if (tid < 64) {
        int c = tid;
        float var = (s_var[0] + s_var[1]) * (1.0f / 64.0f);
        float d = y - mean;
        node_out[bj * 64 + c] = s_x[c] + d * rsqrtf(var + 1e-5f) * na_g[c] + na_beta[c];
    }
}

// ================= launch =================
extern "C" void kernel_launch(void* const* d_in, const int* in_sizes, int n_in,
                              void* d_out, int out_size) {
    (void)in_sizes; (void)n_in; (void)out_size;
    const int*   atom    = (const int*)  d_in[0];
    const float* pos     = (const float*)d_in[1];
    const float* mask    = (const float*)d_in[2];
    const float* emb     = (const float*)d_in[3];
    const float* ne_w    = (const float*)d_in[4];
    const float* ne_b    = (const float*)d_in[5];
    const float* ne_g    = (const float*)d_in[6];
    const float* ne_beta = (const float*)d_in[7];
    const float* ee_w1   = (const float*)d_in[8];
    const float* ee_b1   = (const float*)d_in[9];
    const float* ee_w2   = (const float*)d_in[10];
    const float* ee_b2   = (const float*)d_in[11];
    const float* ee_w3   = (const float*)d_in[12];
    const float* ee_b3   = (const float*)d_in[13];
    const float* ee_g    = (const float*)d_in[14];
    const float* ee_beta = (const float*)d_in[15];
    const float* na_w1   = (const float*)d_in[16];
    const float* na_b1   = (const float*)d_in[17];
    const float* na_w2   = (const float*)d_in[18];
    const float* na_b2   = (const float*)d_in[19];
    const float* na_w3   = (const float*)d_in[20];
    const float* na_b3   = (const float*)d_in[21];
    const float* na_g    = (const float*)d_in[22];
    const float* na_beta = (const float*)d_in[23];

    float* out      = (float*)d_out;
    float* node_out = out;                  // (B,N,D)
    float* edge_out = out + PB * PN * 64;   // (B,N,N,E)

    const int SMEM_EDGE = WIMG_WORDS * 4;   // 57344 B
    cudaFuncSetAttribute(k_edge, cudaFuncAttributeMaxDynamicSharedMemorySize, SMEM_EDGE);

    k_node_prep<<<PB * PN / 4, dim3(64, 4)>>>(atom, emb, ne_w, ne_b, ne_g, ne_beta, ee_w1);
    k_wprep<<<1, 256>>>(ee_w1, ee_w2, ee_w3);
    k_edge<<<PB * PN, 256, SMEM_EDGE>>>(pos, mask, ee_b1, ee_b2, ee_b3,
                                        ee_g, ee_beta, edge_out);
    k_agg1<<<PB * 32, 256>>>(edge_out, mask);
    k_agg_node<<<PB * PN, 256>>>(atom, na_w1, na_b1, na_w2, na_b2,
                                 na_w3, na_b3, na_g, na_beta, node_out);
}

// round 17
// speedup vs baseline: 1.5214x; 1.1405x over previous
#include <cuda_runtime.h>
#include <cuda_bf16.h>
#include <math.h>
#include <stdint.h>

#define PB 8
#define PN 256

// ---------------- scratch ----------------
__device__ float g_node[PB * PN * 64];
__device__ float g_T[PB * PN * 64];
__device__ float g_S[PB * PN * 64];     // node@Ws + b1 (fp32, indexed by j)
// fragment-ordered weights, vec4 interleaved: word = ((t*S+s)*32+lane)*4 + {h0,h1,l0,l1}
__device__ __align__(16) uint32_t g_wimg[10240];
// agg partials: 64 i-groups x 8 b x (256 j x 64 c)
__device__ __align__(16) float g_part[512 * 16384];
__device__ float m_part[512 * 256];

#define W1_O 0          // S=2: 16*32*4 = 2048 words
#define W2_O 2048       // S=4: 32*32*4 = 4096
#define W3_O 6144       // S=4: 4096
#define WIMG_WORDS 10240

// res.lo = x0, res.hi = x1
#define PACK_BF16X2(res, x0, x1) \
    asm("cvt.rn.satfinite.bf16x2.f32 %0, %1, %2;" : "=r"(res) : "f"(x1), "f"(x0))

#define MMA_BF16(c, a, b0, b1) \
    asm volatile("mma.sync.aligned.m16n8k16.row.col.f32.bf16.bf16.f32 " \
        "{%0,%1,%2,%3}, {%4,%5,%6,%7}, {%8,%9}, {%0,%1,%2,%3};" \
        : "+f"((c)[0]), "+f"((c)[1]), "+f"((c)[2]), "+f"((c)[3]) \
        : "r"((a)[0]), "r"((a)[1]), "r"((a)[2]), "r"((a)[3]), "r"(b0), "r"(b1))

// exp(-x) for x >= 0, poly exp2 (no MUFU), rel err ~1.5e-4
__device__ __forceinline__ float fexp_neg(float x) {
    float y = -x * 1.44269504f;
    if (y < -126.0f) return 0.0f;
    float n = floorf(y);
    float f = y - n;
    float p = 1.0f + f * (0.6931472f + f * (0.2402265f + f * (0.0555041f +
              f * (0.0096181f + f * 0.0013333f))));
    return p * __int_as_float(((int)n + 127) << 23);
}

__device__ __forceinline__ void split_pack(float x0, float x1, uint32_t& h, uint32_t& l) {
    PACK_BF16X2(h, x0, x1);
    float e0 = x0 - __bfloat162float(__float2bfloat16_rn(x0));
    float e1 = x1 - __bfloat162float(__float2bfloat16_rn(x1));
    PACK_BF16X2(l, e0, e1);
}

// ================= Kernel 1: node embed + LN + S/T precompute =================
__global__ __launch_bounds__(256) void k_node_prep(
    const int* __restrict__ atom, const float* __restrict__ emb,
    const float* __restrict__ ne_w, const float* __restrict__ ne_b,
    const float* __restrict__ ne_g, const float* __restrict__ ne_beta,
    const float* __restrict__ ee_w1, const float* __restrict__ ee_b1)
{
    int y = threadIdx.y, c = threadIdx.x;
    int row = blockIdx.x * 4 + y;
    __shared__ float s_in[4][64], s_node[4][64], s_red[4][2];

    int a = atom[row];
    s_in[y][c] = fmaxf(emb[a * 64 + c], 0.0f);
    __syncthreads();

    float acc = ne_b[c];
#pragma unroll 8
    for (int k = 0; k < 64; k++) acc += s_in[y][k] * ne_w[k * 64 + c];

    float v = acc;
#pragma unroll
    for (int o = 16; o; o >>= 1) v += __shfl_xor_sync(0xffffffffu, v, o);
    if ((c & 31) == 0) s_red[y][c >> 5] = v;
    __syncthreads();
    float mean = (s_red[y][0] + s_red[y][1]) * (1.0f / 64.0f);
    float d = acc - mean;
    v = d * d;
#pragma unroll
    for (int o = 16; o; o >>= 1) v += __shfl_xor_sync(0xffffffffu, v, o);
    __syncthreads();
    if ((c & 31) == 0) s_red[y][c >> 5] = v;
    __syncthreads();
    float var = (s_red[y][0] + s_red[y][1]) * (1.0f / 64.0f);
    float nv = d * rsqrtf(var + 1e-5f) * ne_g[c] + ne_beta[c];

    g_node[row * 64 + c] = nv;
    s_node[y][c] = nv;
    __syncthreads();

    // S = node@Ws + b1 (rows 0..63), T = node@Wt (rows 64..127)
    float sacc = ee_b1[c];
    float tacc = 0.0f;
#pragma unroll 8
    for (int k = 0; k < 64; k++) {
        float x = s_node[y][k];
        sacc += x * ee_w1[k * 64 + c];
        tacc += x * ee_w1[(64 + k) * 64 + c];
    }
    g_S[row * 64 + c] = sacc;
    g_T[row * 64 + c] = tacc;
}

// ================= Kernel 1b: fragment-ordered weight images (vec4) =================
__device__ __forceinline__ void wimg_put4(uint32_t* base, int ts, int lane, int reg,
                                          float w0, float w1) {
    uint32_t h, l;
    split_pack(w0, w1, h, l);
    base[(ts * 32 + lane) * 4 + reg]     = h;
    base[(ts * 32 + lane) * 4 + 2 + reg] = l;
}

__global__ __launch_bounds__(256) void k_wprep(
    const float* __restrict__ ee_w1, const float* __restrict__ ee_w2,
    const float* __restrict__ ee_w3)
{
    int tid = threadIdx.x;
    // Layer 1: S=2 (rbf only, K=32), Wr = ee_w1 rows 128..159. ts = t*2+s.
    for (int idx = tid; idx < 1024; idx += 256) {
        int reg = idx & 1, lane = (idx >> 1) & 31, ts = idx >> 6;
        int s = ts & 1, t = ts >> 1;
        int k = s * 16 + (lane & 3) * 2 + reg * 8;
        int n = t * 8 + (lane >> 2);
        wimg_put4(&g_wimg[W1_O], ts, lane, reg,
                  ee_w1[(128 + k) * 64 + n], ee_w1[(129 + k) * 64 + n]);
    }
    // Layers 2/3: S=4, K=64. ts = t*4+s.
    for (int idx = tid; idx < 2048; idx += 256) {
        int reg = idx & 1, lane = (idx >> 1) & 31, ts = idx >> 6;
        int s = ts & 3, t = ts >> 2;
        int k = s * 16 + (lane & 3) * 2 + reg * 8;
        int n = t * 8 + (lane >> 2);
        wimg_put4(&g_wimg[W2_O], ts, lane, reg, ee_w2[k * 64 + n], ee_w2[(k + 1) * 64 + n]);
        wimg_put4(&g_wimg[W3_O], ts, lane, reg, ee_w3[k * 64 + n], ee_w3[(k + 1) * 64 + n]);
    }
}

// rbf pair for cols k, k+1 -> packed hi/lo
__device__ __forceinline__ void rbf_pair(float dist, float mk, int k,
                                         uint32_t& h, uint32_t& l) {
    float t0 = (dist - (20.0f / 31.0f) * (float)k) * 1.6f;
    float t1 = (dist - (20.0f / 31.0f) * (float)(k + 1)) * 1.6f;
    float x0 = fexp_neg(t0 * t0) * mk;
    float x1 = fexp_neg(t1 * t1) * mk;
    split_pack(x0, x1, h, l);
}

// bias+relu+split: C frags -> next layer A frags (all registers)
__device__ __forceinline__ void xform(
    float c[8][4], const float* __restrict__ bias, int cw,
    uint32_t h0[8], uint32_t h1[8], uint32_t l0[8], uint32_t l1[8])
{
#pragma unroll
    for (int t = 0; t < 8; t++) {
        float2 bv = *(const float2*)&bias[t * 8 + cw * 2];
        float x0 = fmaxf(c[t][0] + bv.x, 0.0f);
        float x1 = fmaxf(c[t][1] + bv.y, 0.0f);
        float x2 = fmaxf(c[t][2] + bv.x, 0.0f);
        float x3 = fmaxf(c[t][3] + bv.y, 0.0f);
        split_pack(x0, x1, h0[t], l0[t]);
        split_pack(x2, x3, h1[t], l1[t]);
    }
}

// ================= Kernel 2: register-chained mma.sync edge MLP =================
// Block per (b,i), 256 threads, 2 chunks of 128 j's. Layer 1 is K=32 (rbf only);
// S_j + T_i enter via the fp32 epilogue. All activations in registers.
__global__ __launch_bounds__(256, 2) void k_edge(
    const float* __restrict__ pos, const float* __restrict__ mask,
    const float* __restrict__ ee_b2, const float* __restrict__ ee_b3,
    const float* __restrict__ ee_g, const float* __restrict__ ee_beta,
    float* __restrict__ edge_out)
{
    extern __shared__ uint32_t sw[];   // weight image only (40960 B)
    __shared__ float s_Tp[64], s_b2[64], s_b3[64], s_g[64], s_be[64];

    const int tid = threadIdx.x;
    const int wid = tid >> 5;
    const int lane = tid & 31;
    const int q = lane >> 2;
    const int cw = lane & 3;
    const int bi = blockIdx.x;
    const int b = bi >> 8;

    {
        const uint4* src = (const uint4*)g_wimg;
        uint4* dst = (uint4*)sw;
        for (int i = tid; i < WIMG_WORDS / 4; i += 256) dst[i] = src[i];
    }
    if (tid < 64) {
        s_Tp[tid] = g_T[bi * 64 + tid];
        s_b2[tid] = ee_b2[tid];
        s_b3[tid] = ee_b3[tid];
        s_g[tid]  = ee_g[tid];
        s_be[tid] = ee_beta[tid];
    }
    __syncthreads();

    const float px = pos[bi * 3 + 0];
    const float py = pos[bi * 3 + 1];
    const float pz = pos[bi * 3 + 2];

#pragma unroll 1
    for (int jc = 0; jc < 2; jc++) {
        const int r0 = jc * 128 + wid * 16 + q;   // local j of rowset 0 (rowset 1 = +8)
        const int gj0 = b * 256 + r0;
        const int gj1 = gj0 + 8;

        // distances for this thread's two rows
        float d0, mk0, d1, mk1;
        {
            float qx = pos[gj0 * 3 + 0], qy = pos[gj0 * 3 + 1], qz = pos[gj0 * 3 + 2];
            mk0 = mask[bi * 256 + r0];
            float dx = px - qx, dy = py - qy, dz = pz - qz;
            d0 = sqrtf(dx * dx + dy * dy + dz * dz + 1e-10f) * mk0;
            qx = pos[gj1 * 3 + 0]; qy = pos[gj1 * 3 + 1]; qz = pos[gj1 * 3 + 2];
            mk1 = mask[bi * 256 + r0 + 8];
            dx = px - qx; dy = py - qy; dz = pz - qz;
            d1 = sqrtf(dx * dx + dy * dy + dz * dz + 1e-10f) * mk1;
        }

        float c[8][4] = {};

        // ---- layer 1 (K=32, rbf only) ----
#pragma unroll
        for (int s = 0; s < 2; s++) {
            uint32_t ah[4], al[4];
            int k = s * 16 + cw * 2;
            rbf_pair(d0, mk0, k,     ah[0], al[0]);
            rbf_pair(d1, mk1, k,     ah[1], al[1]);
            rbf_pair(d0, mk0, k + 8, ah[2], al[2]);
            rbf_pair(d1, mk1, k + 8, ah[3], al[3]);
#pragma unroll
            for (int t = 0; t < 8; t++) {
                uint4 bv = *(const uint4*)&sw[W1_O + ((t * 2 + s) * 32 + lane) * 4];
                MMA_BF16(c[t], ah, bv.x, bv.y);
                MMA_BF16(c[t], al, bv.x, bv.y);
                MMA_BF16(c[t], ah, bv.z, bv.w);
            }
        }

        // ---- epilogue 1: + T_i + S_j (fp32), relu, split ----
        uint32_t h0[8], h1[8], l0[8], l1[8];
#pragma unroll
        for (int t = 0; t < 8; t++) {
            float2 tp  = *(const float2*)&s_Tp[t * 8 + cw * 2];
            float2 sv0 = *(const float2*)&g_S[gj0 * 64 + t * 8 + cw * 2];
            float2 sv1 = *(const float2*)&g_S[gj1 * 64 + t * 8 + cw * 2];
            float x0 = fmaxf(c[t][0] + tp.x + sv0.x, 0.0f);
            float x1 = fmaxf(c[t][1] + tp.y + sv0.y, 0.0f);
            float x2 = fmaxf(c[t][2] + tp.x + sv1.x, 0.0f);
            float x3 = fmaxf(c[t][3] + tp.y + sv1.y, 0.0f);
            split_pack(x0, x1, h0[t], l0[t]);
            split_pack(x2, x3, h1[t], l1[t]);
        }

        // ---- layer 2 (K=64) ----
#pragma unroll
        for (int t = 0; t < 8; t++) { c[t][0] = 0.f; c[t][1] = 0.f; c[t][2] = 0.f; c[t][3] = 0.f; }
#pragma unroll
        for (int s = 0; s < 4; s++) {
            uint32_t ah[4] = {h0[2 * s], h1[2 * s], h0[2 * s + 1], h1[2 * s + 1]};
            uint32_t al[4] = {l0[2 * s], l1[2 * s], l0[2 * s + 1], l1[2 * s + 1]};
#pragma unroll
            for (int t = 0; t < 8; t++) {
                uint4 bv = *(const uint4*)&sw[W2_O + ((t * 4 + s) * 32 + lane) * 4];
                MMA_BF16(c[t], ah, bv.x, bv.y);
                MMA_BF16(c[t], al, bv.x, bv.y);
                MMA_BF16(c[t], ah, bv.z, bv.w);
            }
        }
        xform(c, s_b2, cw, h0, h1, l0, l1);

        // ---- layer 3 (K=64) ----
#pragma unroll
        for (int t = 0; t < 8; t++) { c[t][0] = 0.f; c[t][1] = 0.f; c[t][2] = 0.f; c[t][3] = 0.f; }
#pragma unroll
        for (int s = 0; s < 4; s++) {
            uint32_t ah[4] = {h0[2 * s], h1[2 * s], h0[2 * s + 1], h1[2 * s + 1]};
            uint32_t al[4] = {l0[2 * s], l1[2 * s], l0[2 * s + 1], l1[2 * s + 1]};
#pragma unroll
            for (int t = 0; t < 8; t++) {
                uint4 bv = *(const uint4*)&sw[W3_O + ((t * 4 + s) * 32 + lane) * 4];
                MMA_BF16(c[t], ah, bv.x, bv.y);
                MMA_BF16(c[t], al, bv.x, bv.y);
                MMA_BF16(c[t], ah, bv.z, bv.w);
            }
        }

        // ---- bias + LayerNorm + store ----
#pragma unroll
        for (int t = 0; t < 8; t++) {
            float2 bv = *(const float2*)&s_b3[t * 8 + cw * 2];
            c[t][0] += bv.x; c[t][1] += bv.y;
            c[t][2] += bv.x; c[t][3] += bv.y;
        }
        float s0 = 0.0f, s1 = 0.0f;
#pragma unroll
        for (int t = 0; t < 8; t++) { s0 += c[t][0] + c[t][1]; s1 += c[t][2] + c[t][3]; }
        s0 += __shfl_xor_sync(0xffffffffu, s0, 1);
        s0 += __shfl_xor_sync(0xffffffffu, s0, 2);
        s1 += __shfl_xor_sync(0xffffffffu, s1, 1);
        s1 += __shfl_xor_sync(0xffffffffu, s1, 2);
        float m0 = s0 * (1.0f / 64.0f), m1 = s1 * (1.0f / 64.0f);
        float q0 = 0.0f, q1 = 0.0f;
#pragma unroll
        for (int t = 0; t < 8; t++) {
            float e0 = c[t][0] - m0, e1 = c[t][1] - m0;
            float e2 = c[t][2] - m1, e3 = c[t][3] - m1;
            q0 += e0 * e0 + e1 * e1;
            q1 += e2 * e2 + e3 * e3;
        }
        q0 += __shfl_xor_sync(0xffffffffu, q0, 1);
        q0 += __shfl_xor_sync(0xffffffffu, q0, 2);
        q1 += __shfl_xor_sync(0xffffffffu, q1, 1);
        q1 += __shfl_xor_sync(0xffffffffu, q1, 2);
        float i0 = rsqrtf(q0 * (1.0f / 64.0f) + 1e-5f);
        float i1 = rsqrtf(q1 * (1.0f / 64.0f) + 1e-5f);
        float* d0p = edge_out + (size_t)(bi * 256 + r0) * 64;
        float* d1p = d0p + 8 * 64;
#pragma unroll
        for (int t = 0; t < 8; t++) {
            int n = t * 8 + cw * 2;
            float2 gv = *(const float2*)&s_g[n];
            float2 bev = *(const float2*)&s_be[n];
            float2 o0, o1;
            o0.x = (c[t][0] - m0) * i0 * gv.x + bev.x;
            o0.y = (c[t][1] - m0) * i0 * gv.y + bev.y;
            o1.x = (c[t][2] - m1) * i1 * gv.x + bev.x;
            o1.y = (c[t][3] - m1) * i1 * gv.y + bev.y;
            *(float2*)&d0p[n] = o0;
            *(float2*)&d1p[n] = o1;
        }
    }
}

// ================= Kernel 3a: contiguous partial aggregation =================
// Block per (b, p): p = i-group of 4. Streams 4 contiguous 64KB (j,c) planes.
__global__ __launch_bounds__(256) void k_agg1(
    const float* __restrict__ edge, const float* __restrict__ mask)
{
    int bp = blockIdx.x;
    int b = bp >> 6, p = bp & 63;
    int tid = threadIdx.x;

    float4 acc[16];
#pragma unroll
    for (int s = 0; s < 16; s++) acc[s] = make_float4(0.f, 0.f, 0.f, 0.f);

    const float4* base = (const float4*)(edge + (size_t)(b * 256 + p * 4) * 16384);
#pragma unroll 1
    for (int i = 0; i < 4; i++) {
        const float4* pl = base + (size_t)i * 4096;
#pragma unroll
        for (int s = 0; s < 16; s++) {
            float4 v = pl[s * 256 + tid];
            acc[s].x += v.x; acc[s].y += v.y; acc[s].z += v.z; acc[s].w += v.w;
        }
    }
    float4* out = (float4*)(g_part + (size_t)bp * 16384);
#pragma unroll
    for (int s = 0; s < 16; s++) out[s * 256 + tid] = acc[s];

    float ms = 0.0f;
    const float* mp = mask + b * 65536 + p * 4 * 256 + tid;
#pragma unroll
    for (int i = 0; i < 4; i++) ms += mp[i * 256];
    m_part[bp * 256 + tid] = ms;
}

// ================= Kernel 3b: partial reduce + node MLP + residual =================
__global__ __launch_bounds__(256) void k_agg_node(
    const int* __restrict__ atom,
    const float* __restrict__ na_w1, const float* __restrict__ na_b1,
    const float* __restrict__ na_w2, const float* __restrict__ na_b2,
    const float* __restrict__ na_w3, const float* __restrict__ na_b3,
    const float* __restrict__ na_g, const float* __restrict__ na_beta,
    float* __restrict__ node_out)
{
    int bj = blockIdx.x;
    int b = bj >> 8, j = bj & 255;
    int tid = threadIdx.x;
    int cq = tid & 15, pt = tid >> 4;    // 16 cq x 16 pt
    __shared__ float s_part[16][68];
    __shared__ float s_x[128], s_h[64], s_h2[64], s_red[2], s_var[2], s_ms[1];

    // reduce 64 partials: pt handles p = pt, pt+16, pt+32, pt+48
    {
        const float* g0 = g_part + (size_t)(b * 64 + pt) * 16384 + j * 64 + cq * 4;
        float4 a = make_float4(0.f, 0.f, 0.f, 0.f);
#pragma unroll
        for (int r = 0; r < 4; r++) {
            float4 v = *(const float4*)(g0 + (size_t)r * 16 * 16384);
            a.x += v.x; a.y += v.y; a.z += v.z; a.w += v.w;
        }
        *(float4*)&s_part[pt][cq * 4] = a;
    }
    if (tid < 32) {
        float ms = m_part[(b * 64 + tid) * 256 + j] + m_part[(b * 64 + 32 + tid) * 256 + j];
#pragma unroll
        for (int o = 16; o; o >>= 1) ms += __shfl_xor_sync(0xffffffffu, ms, o);
        if (tid == 0) s_ms[0] = ms;
    }
    __syncthreads();

    if (tid < 64) {
        int c = tid;
        float acc = 0.0f;
#pragma unroll
        for (int t = 0; t < 16; t++) acc += s_part[t][c];
        float gate = (atom[bj] >= 1) ? 1.0f : 0.0f;
        s_x[c]      = g_node[bj * 64 + c];
        s_x[64 + c] = acc / (s_ms[0] + 1e-10f) * gate;
    }
    __syncthreads();

    float y = 0.0f;
    if (tid < 64) {
        int c = tid;
        y = na_b1[c];
#pragma unroll 8
        for (int k = 0; k < 128; k++) y += s_x[k] * na_w1[k * 64 + c];
        s_h[c] = fmaxf(y, 0.0f);
    }
    __syncthreads();
    if (tid < 64) {
        int c = tid;
        y = na_b2[c];
#pragma unroll 8
        for (int k = 0; k < 64; k++) y += s_h[k] * na_w2[k * 64 + c];
        s_h2[c] = fmaxf(y, 0.0f);
    }
    __syncthreads();
    if (tid < 64) {
        int c = tid;
        y = na_b3[c];
#pragma unroll 8
        for (int k = 0; k < 64; k++) y += s_h2[k] * na_w3[k * 64 + c];
        float v = y;
#pragma unroll
        for (int o = 16; o; o >>= 1) v += __shfl_xor_sync(0xffffffffu, v, o);
        if ((c & 31) == 0) s_red[c >> 5] = v;
    }
    __syncthreads();
    float mean = (s_red[0] + s_red[1]) * (1.0f / 64.0f);
    if (tid < 64) {
        int c = tid;
        float d = y - mean;
        float v = d * d;
#pragma unroll
        for (int o = 16; o; o >>= 1) v += __shfl_xor_sync(0xffffffffu, v, o);
        if ((c & 31) == 0) s_var[c >> 5] = v;
    }
    __syncthreads();
    if (tid < 64) {
        int c = tid;
        float var = (s_var[0] + s_var[1]) * (1.0f / 64.0f);
        float d = y - mean;
        node_out[bj * 64 + c] = s_x[c] + d * rsqrtf(var + 1e-5f) * na_g[c] + na_beta[c];
    }
}

// ================= launch =================
extern "C" void kernel_launch(void* const* d_in, const int* in_sizes, int n_in,
                              void* d_out, int out_size) {
    (void)in_sizes; (void)n_in; (void)out_size;
    const int*   atom    = (const int*)  d_in[0];
    const float* pos     = (const float*)d_in[1];
    const float* mask    = (const float*)d_in[2];
    const float* emb     = (const float*)d_in[3];
    const float* ne_w    = (const float*)d_in[4];
    const float* ne_b    = (const float*)d_in[5];
    const float* ne_g    = (const float*)d_in[6];
    const float* ne_beta = (const float*)d_in[7];
    const float* ee_w1   = (const float*)d_in[8];
    const float* ee_b1   = (const float*)d_in[9];
    const float* ee_w2   = (const float*)d_in[10];
    const float* ee_b2   = (const float*)d_in[11];
    const float* ee_w3   = (const float*)d_in[12];
    const float* ee_b3   = (const float*)d_in[13];
    const float* ee_g    = (const float*)d_in[14];
    const float* ee_beta = (const float*)d_in[15];
    const float* na_w1   = (const float*)d_in[16];
    const float* na_b1   = (const float*)d_in[17];
    const float* na_w2   = (const float*)d_in[18];
    const float* na_b2   = (const float*)d_in[19];
    const float* na_w3   = (const float*)d_in[20];
    const float* na_b3   = (const float*)d_in[21];
    const float* na_g    = (const float*)d_in[22];
    const float* na_beta = (const float*)d_in[23];

    float* out      = (float*)d_out;
    float* node_out = out;                  // (B,N,D)
    float* edge_out = out + PB * PN * 64;   // (B,N,N,E)

    const int SMEM_EDGE = WIMG_WORDS * 4;   // 40960 B
    cudaFuncSetAttribute(k_edge, cudaFuncAttributeMaxDynamicSharedMemorySize, SMEM_EDGE);

    k_node_prep<<<PB * PN / 4, dim3(64, 4)>>>(atom, emb, ne_w, ne_b, ne_g, ne_beta,
                                              ee_w1, ee_b1);
    k_wprep<<<1, 256>>>(ee_w1, ee_w2, ee_w3);
    k_edge<<<PB * PN, 256, SMEM_EDGE>>>(pos, mask, ee_b2, ee_b3,
                                        ee_g, ee_beta, edge_out);
    k_agg1<<<PB * 64, 256>>>(edge_out, mask);
    k_agg_node<<<PB * PN, 256>>>(atom, na_w1, na_b1, na_w2, na_b2,
                                 na_w3, na_b3, na_g, na_beta, node_out);
}